// round 15
// baseline (speedup 1.0000x reference)
#include <cuda_runtime.h>
#include <cuda_fp16.h>
#include <math.h>

#define D      768
#define T      1024
#define BATCH  8
#define M_TOT  (BATCH*T)   // 8192
#define NH     12
#define DH     64

// ---------------- scratch (device globals: alloc-free rule) ----------------
__device__ __half g_xn [(size_t)M_TOT * D];            // fp16 single
__device__ __half g_q16[(size_t)M_TOT * NH * 64];      // [tok][head][64], QSCALE folded
__device__ __half g_k16[(size_t)M_TOT * NH * 64];
__device__ __half g_v16[(size_t)M_TOT * NH * 64];
__device__ float  g_g  [(size_t)M_TOT * D];
__device__ __half g_y16[(size_t)M_TOT * D];
__device__ __half g_wq_hi[D*D];
__device__ __half g_wk_hi[D*D];
__device__ __half g_wv_hi[D*D];
__device__ __half g_wg_hi[D*D];
__device__ __half g_wo_hi[D*D], g_wo_lo[D*D];

#define QSCALE 0.18033688011112042f

// ---------------- PTX helpers -----------------------------------------------
#define CPASYNC(dst, src) \
    asm volatile("cp.async.cg.shared.global [%0], [%1], 16;" :: "r"(dst), "l"(src) : "memory")
#define CP_COMMIT() asm volatile("cp.async.commit_group;" ::: "memory")
#define CP_WAIT(n)  asm volatile("cp.async.wait_group %0;" :: "n"(n) : "memory")
#define LDSM4(R0,R1,R2,R3,A) \
    asm volatile("ldmatrix.sync.aligned.m8n8.x4.shared.b16 {%0,%1,%2,%3}, [%4];" \
                 : "=r"(R0), "=r"(R1), "=r"(R2), "=r"(R3) : "r"(A))
#define LDSM4T(R0,R1,R2,R3,A) \
    asm volatile("ldmatrix.sync.aligned.m8n8.x4.trans.shared.b16 {%0,%1,%2,%3}, [%4];" \
                 : "=r"(R0), "=r"(R1), "=r"(R2), "=r"(R3) : "r"(A))

__device__ __forceinline__ void mma_f16(float* d, const unsigned* a, const unsigned* b) {
    asm volatile(
        "mma.sync.aligned.m16n8k16.row.col.f32.f16.f16.f32 "
        "{%0,%1,%2,%3}, {%4,%5,%6,%7}, {%8,%9}, {%0,%1,%2,%3};"
        : "+f"(d[0]), "+f"(d[1]), "+f"(d[2]), "+f"(d[3])
        : "r"(a[0]), "r"(a[1]), "r"(a[2]), "r"(a[3]), "r"(b[0]), "r"(b[1]));
}

__device__ __forceinline__ unsigned exp2_f16x2(float a, float b) {
    unsigned r;
    asm volatile("{\n\t.reg .b32 t;\n\t"
                 "cvt.rn.f16x2.f32 t, %2, %1;\n\t"
                 "ex2.approx.f16x2 %0, t;\n\t}"
                 : "=r"(r) : "f"(a), "f"(b));
    return r;
}
__device__ __forceinline__ unsigned hadd2u(unsigned a, unsigned b) {
    unsigned r;
    asm volatile("add.f16x2 %0, %1, %2;" : "=r"(r) : "r"(a), "r"(b));
    return r;
}

// ---------------- weight prep: Wo split hi/lo; q/k/v/g hi only ----------------
struct SplitArgs {
    const float* w[5];
    __half* h[5];
    __half* l[5];
};

__global__ __launch_bounds__(256)
void split5(SplitArgs a)
{
    const int i = blockIdx.x * 256 + threadIdx.x;
    if (i >= D * D) return;
    const int m = blockIdx.y;
    const float v = a.w[m][i];
    const __half h = __float2half_rn(v);
    a.h[m][i] = h;
    if (m == 4)
        a.l[m][i] = __float2half_rn(v - __half2float(h));
}

// ---------------- LayerNorm: coalesced transpose-tile ------------------------
#define LN_SMEMB (768 * 33 * 4 + 256)

__global__ __launch_bounds__(256)
void ln_kernel(const float* __restrict__ x,
               const float* __restrict__ gamma,
               const float* __restrict__ beta)
{
    extern __shared__ float lsm[];
    float* st = lsm;
    float* mu = lsm + 768 * 33;
    float* rs = mu + 32;

    const int tid = threadIdx.x;
    const int b   = blockIdx.x >> 5;
    const int t0  = (blockIdx.x & 31) * 32;
    const float* xp = x + (size_t)b * D * T + t0;

    float gm[3], bt[3];
    #pragma unroll
    for (int j = 0; j < 3; ++j) {
        gm[j] = gamma[j * 256 + tid];
        bt[j] = beta [j * 256 + tid];
    }

    #pragma unroll 4
    for (int i = 0; i < 96; ++i) {
        const int idx = i * 256 + tid;
        const int c   = idx >> 5;
        const int tt  = idx & 31;
        st[c * 33 + tt] = xp[(size_t)c * T + tt];
    }
    __syncthreads();

    const int wid = tid >> 5, lane = tid & 31;
    #pragma unroll
    for (int rep = 0; rep < 4; ++rep) {
        const int tt = wid + rep * 8;
        float s = 0.f, ss = 0.f;
        #pragma unroll
        for (int j = 0; j < 24; ++j) {
            const float v = st[(lane + 32 * j) * 33 + tt];
            s += v; ss += v * v;
        }
        #pragma unroll
        for (int o = 16; o > 0; o >>= 1) {
            s  += __shfl_xor_sync(0xffffffffu, s,  o);
            ss += __shfl_xor_sync(0xffffffffu, ss, o);
        }
        if (lane == 0) {
            const float m = s * (1.0f / (float)D);
            const float var = ss * (1.0f / (float)D) - m * m;
            mu[tt] = m;
            rs[tt] = rsqrtf(var + 1e-5f);
        }
    }
    __syncthreads();

    for (int tt = 0; tt < 32; ++tt) {
        const float m = mu[tt], r = rs[tt];
        __half* o = g_xn + (size_t)(b * T + t0 + tt) * D;
        #pragma unroll
        for (int j = 0; j < 3; ++j) {
            const int c = j * 256 + tid;
            o[c] = __float2half_rn((st[c * 33 + tt] - m) * r * gm[j] + bt[j]);
        }
    }
}

// ---------------- shared GEMM constants ----------------------------------------
#define URO    20
#define CROWB  80
#define CSTGB  10240
#define STGB_W 30720
#define STGB_Q 20480
#define QKVG_SMEM (5 * STGB_Q)  // 102400
#define WO_SMEM   (3 * STGB_W)  // 92160

struct GemmArgs {
    const __half* Bh[4];
    const __half* Bl[4];
    const float* bias[4];
    float*       C[4];
};

// ---------------- qkvg GEMM: 4 warps x 64x64 warp tiles, 1-pass ---------------
__global__ __launch_bounds__(128, 2)
void qkvg_mma(const __half* __restrict__ Ag, GemmArgs args)
{
    extern __shared__ unsigned smu[];
    const int tid = threadIdx.x;
    const int m0  = blockIdx.y * 128;
    const int region = blockIdx.x / 6;
    const int nloc0  = (blockIdx.x % 6) * 128;
    const __half* Bh = args.Bh[region];
    const float* bias = args.bias[region];
    float*       C    = args.C[region];

    const unsigned sbase = (unsigned)__cvta_generic_to_shared(smu);

    auto load_stage = [&](int kt, int buf) {
        #pragma unroll
        for (int i = 0; i < 2; ++i) {
            const int id  = tid + i * 128;
            const int rw  = id >> 1;
            const int ch0 = (id & 1) * 16;
            const __half* pa = Ag + (size_t)(m0 + rw) * D + ch0 + kt;
            const __half* pb = Bh + (size_t)(nloc0 + rw) * D + ch0 + kt;
            const unsigned b0 = sbase + (unsigned)buf * STGB_Q +
                                (unsigned)(rw * CROWB + ch0 * 2);
            CPASYNC(b0,           pa);
            CPASYNC(b0 + 16u,     pa + 8);
            CPASYNC(b0 + CSTGB,       pb);
            CPASYNC(b0 + CSTGB + 16u, pb + 8);
        }
        CP_COMMIT();
    };

    const int w    = tid >> 5;
    const int lane = tid & 31;
    const int wm   = w >> 1;        // 0..1
    const int wn   = w & 1;         // 0..1
    const int lr   = lane >> 2;
    const int lc   = lane & 3;

    const int aRow  = (lane & 7) + ((lane & 8) ? 8 : 0);
    const int aColU = (lane & 16) ? 4 : 0;
    const int bRow  = (lane & 7) + ((lane & 16) ? 8 : 0);
    const int bColU = (lane & 8) ? 4 : 0;
    const unsigned aOff = (unsigned)(((wm * 64 + aRow) * URO + aColU) * 4);
    const unsigned bOff = (unsigned)(((wn * 64 + bRow) * URO + bColU) * 4);

    float acc[4][8][4];
    #pragma unroll
    for (int i = 0; i < 4; i++)
        #pragma unroll
        for (int j = 0; j < 8; j++)
            #pragma unroll
            for (int q = 0; q < 4; q++) acc[i][j][q] = 0.f;

    const int NIT = D / 32;   // 24
    #pragma unroll
    for (int s = 0; s < 4; ++s)
        load_stage(s * 32, s);

    for (int it = 0; it < NIT; ++it) {
        const int rem = NIT - 1 - it;
        if      (rem >= 3) { CP_WAIT(3); }
        else if (rem == 2) { CP_WAIT(2); }
        else if (rem == 1) { CP_WAIT(1); }
        else               { CP_WAIT(0); }
        __syncthreads();
        if (it + 4 < NIT)
            load_stage((it + 4) * 32, (it + 4) % 5);

        const unsigned stgb = sbase + (unsigned)((it % 5) * STGB_Q);

        #pragma unroll
        for (int ks = 0; ks < 2; ++ks) {
            const unsigned ko = (unsigned)(ks * 32);
            const unsigned aA = stgb + aOff + ko;
            const unsigned bB = stgb + CSTGB + bOff + ko;

            unsigned ah[4][4];
            #pragma unroll
            for (int mt = 0; mt < 4; ++mt)
                LDSM4(ah[mt][0], ah[mt][1], ah[mt][2], ah[mt][3],
                      aA + (unsigned)(mt * 16 * URO * 4));

            unsigned bh[8][2];
            #pragma unroll
            for (int j = 0; j < 4; ++j) {
                unsigned r0, r1, r2, r3;
                LDSM4(r0, r1, r2, r3, bB + (unsigned)(j * 16 * URO * 4));
                bh[2*j][0] = r0; bh[2*j][1] = r1;
                bh[2*j+1][0] = r2; bh[2*j+1][1] = r3;
            }
            #pragma unroll
            for (int mt = 0; mt < 4; ++mt)
                #pragma unroll
                for (int nt = 0; nt < 8; ++nt)
                    mma_f16(acc[mt][nt], ah[mt], bh[nt]);
        }
    }

    #pragma unroll
    for (int mt = 0; mt < 4; ++mt) {
        const int r = m0 + wm * 64 + mt * 16 + lr;
        #pragma unroll
        for (int nt = 0; nt < 8; ++nt) {
            const int n = nloc0 + wn * 64 + nt * 8 + lc * 2;
            float v00 = acc[mt][nt][0] + bias[n];
            float v01 = acc[mt][nt][1] + bias[n + 1];
            float v10 = acc[mt][nt][2] + bias[n];
            float v11 = acc[mt][nt][3] + bias[n + 1];
            const int head = n >> 6, wi = n & 63;
            if (region < 3) {
                __half* dst = (region == 0) ? g_q16 : (region == 1) ? g_k16 : g_v16;
                const float sc = (region == 0) ? QSCALE : 1.0f;
                const size_t b0 = ((size_t)r * NH + head) * 64 + wi;
                const size_t b1 = ((size_t)(r + 8) * NH + head) * 64 + wi;
                *(__half2*)(dst + b0) = __floats2half2_rn(v00 * sc, v01 * sc);
                *(__half2*)(dst + b1) = __floats2half2_rn(v10 * sc, v11 * sc);
            } else {
                v00 = 1.0f / (1.0f + __expf(-v00));
                v01 = 1.0f / (1.0f + __expf(-v01));
                v10 = 1.0f / (1.0f + __expf(-v10));
                v11 = 1.0f / (1.0f + __expf(-v11));
                *(float2*)(C + (size_t)r * D + n)       = make_float2(v00, v01);
                *(float2*)(C + (size_t)(r + 8) * D + n) = make_float2(v10, v11);
            }
        }
    }
}

// ---------------- Wo GEMM (2-pass hi/lo, 3-stage, transposed output) ----------
__global__ __launch_bounds__(256, 2)
void wo_mma(const __half* __restrict__ Ag,
            const __half* __restrict__ Bh, const __half* __restrict__ Bl,
            const float* __restrict__ bias, float* __restrict__ C)
{
    extern __shared__ unsigned smu[];
    const int tid = threadIdx.x;
    const int m0  = blockIdx.y * 128;
    const int nloc0 = blockIdx.x * 128;

    const int rw  = tid >> 1;
    const int ch0 = (tid & 1) * 16;
    const __half* pA  = Ag + (size_t)(m0 + rw) * D + ch0;
    const __half* pBh = Bh + (size_t)(nloc0 + rw) * D + ch0;
    const __half* pBl = Bl + (size_t)(nloc0 + rw) * D + ch0;
    const unsigned sbase = (unsigned)__cvta_generic_to_shared(smu);
    const unsigned soff  = (unsigned)(rw * CROWB + ch0 * 2);

    auto load_stage = [&](int kt, int buf) {
        const unsigned b0 = sbase + (unsigned)buf * STGB_W + soff;
        CPASYNC(b0,              pA  + kt);
        CPASYNC(b0 + 16u,        pA  + kt + 8);
        CPASYNC(b0 + CSTGB,      pBh + kt);
        CPASYNC(b0 + CSTGB + 16u,pBh + kt + 8);
        CPASYNC(b0 + 2*CSTGB,      pBl + kt);
        CPASYNC(b0 + 2*CSTGB + 16u,pBl + kt + 8);
        CP_COMMIT();
    };

    const int w    = tid >> 5;
    const int lane = tid & 31;
    const int wm   = w >> 2;
    const int wn   = w & 3;
    const int lr   = lane >> 2;
    const int lc   = lane & 3;

    const int aRow  = (lane & 7) + ((lane & 8) ? 8 : 0);
    const int aColU = (lane & 16) ? 4 : 0;
    const int bRow  = (lane & 7) + ((lane & 16) ? 8 : 0);
    const int bColU = (lane & 8) ? 4 : 0;
    const unsigned aOff = (unsigned)(((wm * 64 + aRow) * URO + aColU) * 4);
    const unsigned bOff = (unsigned)(((wn * 32 + bRow) * URO + bColU) * 4);

    float acc[4][4][4];
    #pragma unroll
    for (int i = 0; i < 4; i++)
        #pragma unroll
        for (int j = 0; j < 4; j++)
            #pragma unroll
            for (int q = 0; q < 4; q++) acc[i][j][q] = 0.f;

    const int NIT = D / 32;
    load_stage(0, 0);
    load_stage(32, 1);

    for (int it = 0; it < NIT; ++it) {
        const int rem = NIT - 1 - it;
        if (rem >= 1) { CP_WAIT(1); } else { CP_WAIT(0); }
        __syncthreads();
        if (it + 2 < NIT) load_stage((it + 2) * 32, (it + 2) % 3);

        const unsigned stgb = sbase + (unsigned)((it % 3) * STGB_W);

        #pragma unroll
        for (int ks = 0; ks < 2; ++ks) {
            const unsigned ko = (unsigned)(ks * 32);
            const unsigned aA = stgb + aOff + ko;
            const unsigned bH = stgb + CSTGB + bOff + ko;
            const unsigned bL = stgb + 2 * CSTGB + bOff + ko;

            unsigned ah[4][4];
            #pragma unroll
            for (int mt = 0; mt < 4; ++mt)
                LDSM4(ah[mt][0], ah[mt][1], ah[mt][2], ah[mt][3],
                      aA + (unsigned)(mt * 16 * URO * 4));

            unsigned bh[4][2];
            {
                unsigned r0, r1, r2, r3;
                LDSM4(r0, r1, r2, r3, bH);
                bh[0][0] = r0; bh[0][1] = r1; bh[1][0] = r2; bh[1][1] = r3;
                LDSM4(r0, r1, r2, r3, bH + (unsigned)(16 * URO * 4));
                bh[2][0] = r0; bh[2][1] = r1; bh[3][0] = r2; bh[3][1] = r3;
            }
            #pragma unroll
            for (int mt = 0; mt < 4; ++mt)
                #pragma unroll
                for (int nt = 0; nt < 4; ++nt)
                    mma_f16(acc[mt][nt], ah[mt], bh[nt]);

            unsigned bl[4][2];
            {
                unsigned r0, r1, r2, r3;
                LDSM4(r0, r1, r2, r3, bL);
                bl[0][0] = r0; bl[0][1] = r1; bl[1][0] = r2; bl[1][1] = r3;
                LDSM4(r0, r1, r2, r3, bL + (unsigned)(16 * URO * 4));
                bl[2][0] = r0; bl[2][1] = r1; bl[3][0] = r2; bl[3][1] = r3;
            }
            #pragma unroll
            for (int mt = 0; mt < 4; ++mt)
                #pragma unroll
                for (int nt = 0; nt < 4; ++nt)
                    mma_f16(acc[mt][nt], ah[mt], bl[nt]);
        }
    }

    // coalesced output transpose via smem (stride 132, conflict-free)
    __syncthreads();
    float* sC = (float*)smu;
    #pragma unroll
    for (int mt = 0; mt < 4; ++mt) {
        const int tloc = wm * 64 + mt * 16 + lr;
        #pragma unroll
        for (int nt = 0; nt < 4; ++nt) {
            const int nl = wn * 32 + nt * 8 + lc * 2;
            sC[(size_t)nl * 132 + tloc]           = acc[mt][nt][0] + bias[nloc0 + nl];
            sC[(size_t)(nl + 1) * 132 + tloc]     = acc[mt][nt][1] + bias[nloc0 + nl + 1];
            sC[(size_t)nl * 132 + tloc + 8]       = acc[mt][nt][2] + bias[nloc0 + nl];
            sC[(size_t)(nl + 1) * 132 + tloc + 8] = acc[mt][nt][3] + bias[nloc0 + nl + 1];
        }
    }
    __syncthreads();
    const int b = m0 >> 10, t0 = m0 & 1023;
    #pragma unroll
    for (int i = 0; i < 16; ++i) {
        const int idx = tid + i * 256;
        const int nl  = idx >> 5;
        const int tc  = (idx & 31) * 4;
        const float4 v = *(const float4*)&sC[(size_t)nl * 132 + tc];
        *(float4*)(C + ((size_t)b * D + nloc0 + nl) * T + t0 + tc) = v;
    }
}

// ---------------- fp16 flash attention: KT=64 stages, 2 sub-blocks ------------
#define KT2     64
#define NITER2  (T/KT2)    // 16
#define KVROWH  72
#define STG_B   18432      // K 64x72 (9216) + V 64x72 (9216)
#define ASTAGES 3
#define ATTN_SMEMB (ASTAGES * STG_B)   // 55296

__global__ __launch_bounds__(128, 3)
void attn_mma()
{
    extern __shared__ __half smh[];
    const int tid  = threadIdx.x;
    const int w    = tid >> 5;
    const int lane = tid & 31;
    const int lr   = lane >> 2;
    const int lc   = lane & 3;

    const int qt = blockIdx.x;
    const int h  = blockIdx.y;
    const int b  = blockIdx.z;
    const int row0 = b * T + qt * 128;
    const unsigned sb = (unsigned)__cvta_generic_to_shared(smh);

    auto load_kv = [&](int kt, int stg) {
        #pragma unroll
        for (int i = 0; i < 4; ++i) {
            const int id = tid + i * 128;       // 0..511
            const int tk = id >> 3;             // 0..63
            const int c  = (id & 7) * 8;
            const size_t g = ((size_t)(b * T + kt * KT2 + tk) * NH + h) * 64 + c;
            const unsigned d = sb + (unsigned)(stg * STG_B) +
                               (unsigned)((tk * KVROWH + c) * 2);
            CPASYNC(d,        g_k16 + g);
            CPASYNC(d + 9216, g_v16 + g);
        }
        CP_COMMIT();
    };
    load_kv(0, 0);
    load_kv(1, 1);

    unsigned qh[2][4][4];
    #pragma unroll
    for (int grp = 0; grp < 2; ++grp) {
        const __half* r0p = g_q16 +
            ((size_t)(row0 + w * 32 + grp * 16 + lr) * NH + h) * 64;
        const __half* r1p = r0p + (size_t)8 * NH * 64;
        #pragma unroll
        for (int ks = 0; ks < 4; ++ks) {
            const int c = ks * 16 + 2 * lc;
            qh[grp][ks][0] = *(const unsigned*)(r0p + c);
            qh[grp][ks][1] = *(const unsigned*)(r1p + c);
            qh[grp][ks][2] = *(const unsigned*)(r0p + c + 8);
            qh[grp][ks][3] = *(const unsigned*)(r1p + c + 8);
        }
    }

    float Oa[2][8][4];
    #pragma unroll
    for (int grp = 0; grp < 2; ++grp)
        #pragma unroll
        for (int nt = 0; nt < 8; ++nt)
            #pragma unroll
            for (int q = 0; q < 4; q++) Oa[grp][nt][q] = 0.f;
    float lg[2][2] = {{0.f, 0.f}, {0.f, 0.f}};

    const int kRow  = (lane & 7) + ((lane & 16) ? 8 : 0);
    const int kColH = (lane & 8) ? 8 : 0;
    const int vRow  = (lane & 7) + ((lane & 8) ? 8 : 0);
    const int vColH = (lane & 16) ? 8 : 0;

    for (int kt = 0; kt < NITER2; ++kt) {
        const int rem = NITER2 - 1 - kt;
        if (rem >= 1) { CP_WAIT(1); } else { CP_WAIT(0); }
        __syncthreads();
        if (kt + 2 < NITER2)
            load_kv(kt + 2, (kt + 2) % ASTAGES);

        const unsigned stage = sb + (unsigned)((kt % ASTAGES) * STG_B);

        #pragma unroll
        for (int sub = 0; sub < 2; ++sub) {
            const unsigned sK = stage + (unsigned)(sub * 4608);
            const unsigned sV = stage + 9216u + (unsigned)(sub * 4608);

            // ---- S = Q K^T, both row-groups share K fragments ----
            float sacc[2][4][4];
            #pragma unroll
            for (int grp = 0; grp < 2; ++grp)
                #pragma unroll
                for (int nt = 0; nt < 4; ++nt)
                    #pragma unroll
                    for (int q = 0; q < 4; q++) sacc[grp][nt][q] = 0.f;

            #pragma unroll
            for (int ks = 0; ks < 4; ++ks) {
                unsigned kh[4][2];
                {
                    const unsigned a0 = sK +
                        (unsigned)((kRow * KVROWH + ks * 16 + kColH) * 2);
                    unsigned r0, r1, r2, r3;
                    LDSM4(r0, r1, r2, r3, a0);
                    kh[0][0] = r0; kh[0][1] = r1; kh[1][0] = r2; kh[1][1] = r3;
                    LDSM4(r0, r1, r2, r3, a0 + (unsigned)(16 * KVROWH * 2));
                    kh[2][0] = r0; kh[2][1] = r1; kh[3][0] = r2; kh[3][1] = r3;
                }
                #pragma unroll
                for (int nt = 0; nt < 4; ++nt) {
                    mma_f16(sacc[0][nt], qh[0][ks], kh[nt]);
                    mma_f16(sacc[1][nt], qh[1][ks], kh[nt]);
                }
            }

            // ---- fixed-base softmax per group ----
            unsigned p16[2][2][4];
            #pragma unroll
            for (int grp = 0; grp < 2; ++grp) {
                #pragma unroll
                for (int nt = 0; nt < 4; ++nt) {
                    p16[grp][nt >> 1][(nt & 1) * 2] =
                        exp2_f16x2(sacc[grp][nt][0], sacc[grp][nt][1]);
                    p16[grp][nt >> 1][(nt & 1) * 2 + 1] =
                        exp2_f16x2(sacc[grp][nt][2], sacc[grp][nt][3]);
                }
                const unsigned s0a = hadd2u(p16[grp][0][0], p16[grp][0][2]);
                const unsigned s0b = hadd2u(p16[grp][1][0], p16[grp][1][2]);
                const unsigned s1a = hadd2u(p16[grp][0][1], p16[grp][0][3]);
                const unsigned s1b = hadd2u(p16[grp][1][1], p16[grp][1][3]);
                const float2 f0a = __half22float2(*(const __half2*)&s0a);
                const float2 f0b = __half22float2(*(const __half2*)&s0b);
                const float2 f1a = __half22float2(*(const __half2*)&s1a);
                const float2 f1b = __half22float2(*(const __half2*)&s1b);
                lg[grp][0] += (f0a.x + f0a.y) + (f0b.x + f0b.y);
                lg[grp][1] += (f1a.x + f1a.y) + (f1b.x + f1b.y);
            }

            // ---- O += P V, V fragments shared by 2 row-groups ----
            #pragma unroll
            for (int g = 0; g < 2; ++g) {
                #pragma unroll
                for (int p = 0; p < 4; ++p) {
                    const unsigned a0 = sV +
                        (unsigned)(((g * 16 + vRow) * KVROWH + p * 16 + vColH) * 2);
                    unsigned vh[2][2];
                    unsigned r0, r1, r2, r3;
                    LDSM4T(r0, r1, r2, r3, a0);
                    vh[0][0] = r0; vh[0][1] = r1; vh[1][0] = r2; vh[1][1] = r3;
                    mma_f16(Oa[0][2*p],     p16[0][g], vh[0]);
                    mma_f16(Oa[0][2*p + 1], p16[0][g], vh[1]);
                    mma_f16(Oa[1][2*p],     p16[1][g], vh[0]);
                    mma_f16(Oa[1][2*p + 1], p16[1][g], vh[1]);
                }
            }
        }
    }

    #pragma unroll
    for (int grp = 0; grp < 2; ++grp) {
        float l0 = lg[grp][0], l1 = lg[grp][1];
        l0 += __shfl_xor_sync(0xffffffffu, l0, 1);
        l0 += __shfl_xor_sync(0xffffffffu, l0, 2);
        l1 += __shfl_xor_sync(0xffffffffu, l1, 1);
        l1 += __shfl_xor_sync(0xffffffffu, l1, 2);
        const float inv0 = 1.0f / l0;
        const float inv1 = 1.0f / l1;
        const int gr0 = row0 + w * 32 + grp * 16 + lr;
        const int gr1 = gr0 + 8;
        const int col0 = h * DH;
        #pragma unroll
        for (int nt = 0; nt < 8; ++nt) {
            const int c = col0 + nt * 8 + 2 * lc;
            const float2 ga = *(const float2*)(g_g + (size_t)gr0 * D + c);
            const float2 gb = *(const float2*)(g_g + (size_t)gr1 * D + c);
            *(__half2*)(g_y16 + (size_t)gr0 * D + c) =
                __floats2half2_rn(Oa[grp][nt][0] * inv0 * ga.x,
                                  Oa[grp][nt][1] * inv0 * ga.y);
            *(__half2*)(g_y16 + (size_t)gr1 * D + c) =
                __floats2half2_rn(Oa[grp][nt][2] * inv1 * gb.x,
                                  Oa[grp][nt][3] * inv1 * gb.y);
        }
    }
}

// ---------------- launch --------------------------------------------------------
extern "C" void kernel_launch(void* const* d_in, const int* in_sizes, int n_in,
                              void* d_out, int out_size)
{
    const float* x     = (const float*)d_in[0];
    const float* Wq    = (const float*)d_in[1];
    const float* bq    = (const float*)d_in[2];
    const float* Wk    = (const float*)d_in[3];
    const float* bk    = (const float*)d_in[4];
    const float* Wv    = (const float*)d_in[5];
    const float* bv    = (const float*)d_in[6];
    const float* Wo    = (const float*)d_in[7];
    const float* bo    = (const float*)d_in[8];
    const float* Wg    = (const float*)d_in[9];
    const float* bg    = (const float*)d_in[10];
    const float* gamma = (const float*)d_in[11];
    const float* beta  = (const float*)d_in[12];
    float* out = (float*)d_out;

    void *p;
    __half *xn, *y16;
    __half *wqh,*wkh,*wvh,*wgh,*woh,*wol;
    float *gb_;
    cudaGetSymbolAddress(&p, g_xn);    xn = (__half*)p;
    cudaGetSymbolAddress(&p, g_y16);  y16 = (__half*)p;
    cudaGetSymbolAddress(&p, g_g);    gb_ = (float*)p;
    cudaGetSymbolAddress(&p, g_wq_hi); wqh = (__half*)p;
    cudaGetSymbolAddress(&p, g_wk_hi); wkh = (__half*)p;
    cudaGetSymbolAddress(&p, g_wv_hi); wvh = (__half*)p;
    cudaGetSymbolAddress(&p, g_wg_hi); wgh = (__half*)p;
    cudaGetSymbolAddress(&p, g_wo_hi); woh = (__half*)p;
    cudaGetSymbolAddress(&p, g_wo_lo); wol = (__half*)p;

    cudaFuncSetAttribute(qkvg_mma, cudaFuncAttributeMaxDynamicSharedMemorySize, QKVG_SMEM);
    cudaFuncSetAttribute(wo_mma, cudaFuncAttributeMaxDynamicSharedMemorySize, WO_SMEM);
    cudaFuncSetAttribute(attn_mma, cudaFuncAttributeMaxDynamicSharedMemorySize, ATTN_SMEMB);
    cudaFuncSetAttribute(ln_kernel, cudaFuncAttributeMaxDynamicSharedMemorySize, LN_SMEMB);

    const int wblocks = (D * D + 255) / 256;
    {
        SplitArgs sa;
        sa.w[0] = Wq; sa.h[0] = wqh; sa.l[0] = wqh;
        sa.w[1] = Wk; sa.h[1] = wkh; sa.l[1] = wkh;
        sa.w[2] = Wv; sa.h[2] = wvh; sa.l[2] = wvh;
        sa.w[3] = Wg; sa.h[3] = wgh; sa.l[3] = wgh;
        sa.w[4] = Wo; sa.h[4] = woh; sa.l[4] = wol;
        split5<<<dim3(wblocks, 5), 256>>>(sa);
    }

    ln_kernel<<<256, 256, LN_SMEMB>>>(x, gamma, beta);

    {
        GemmArgs a;
        a.Bh[0] = wqh; a.Bl[0] = wqh; a.bias[0] = bq; a.C[0] = nullptr;
        a.Bh[1] = wkh; a.Bl[1] = wkh; a.bias[1] = bk; a.C[1] = nullptr;
        a.Bh[2] = wvh; a.Bl[2] = wvh; a.bias[2] = bv; a.C[2] = nullptr;
        a.Bh[3] = wgh; a.Bl[3] = wgh; a.bias[3] = bg; a.C[3] = gb_;
        qkvg_mma<<<dim3(24, 64), 128, QKVG_SMEM>>>(xn, a);
    }

    attn_mma<<<dim3(8, NH, BATCH), 128, ATTN_SMEMB>>>();

    wo_mma<<<dim3(6, 64), 256, WO_SMEM>>>(y16, woh, wol, bo, out);
}

// round 16
// speedup vs baseline: 1.2722x; 1.2722x over previous
#include <cuda_runtime.h>
#include <cuda_fp16.h>
#include <math.h>

#define D      768
#define T      1024
#define BATCH  8
#define M_TOT  (BATCH*T)   // 8192
#define NH     12
#define DH     64

// ---------------- scratch (device globals: alloc-free rule) ----------------
__device__ __half g_xn [(size_t)M_TOT * D];            // fp16 single
__device__ __half g_q16[(size_t)M_TOT * NH * 64];      // [tok][head][64], QSCALE folded
__device__ __half g_k16[(size_t)M_TOT * NH * 64];
__device__ __half g_v16[(size_t)M_TOT * NH * 64];
__device__ float  g_g  [(size_t)M_TOT * D];
__device__ __half g_y16[(size_t)M_TOT * D];
__device__ __half g_wq[D*D];
__device__ __half g_wk[D*D];
__device__ __half g_wv[D*D];
__device__ __half g_wg[D*D];
__device__ __half g_wo[D*D];

#define QSCALE 0.18033688011112042f

// ---------------- PTX helpers -----------------------------------------------
#define CPASYNC(dst, src) \
    asm volatile("cp.async.cg.shared.global [%0], [%1], 16;" :: "r"(dst), "l"(src) : "memory")
#define CP_COMMIT() asm volatile("cp.async.commit_group;" ::: "memory")
#define CP_WAIT(n)  asm volatile("cp.async.wait_group %0;" :: "n"(n) : "memory")
#define LDSM4(R0,R1,R2,R3,A) \
    asm volatile("ldmatrix.sync.aligned.m8n8.x4.shared.b16 {%0,%1,%2,%3}, [%4];" \
                 : "=r"(R0), "=r"(R1), "=r"(R2), "=r"(R3) : "r"(A))
#define LDSM4T(R0,R1,R2,R3,A) \
    asm volatile("ldmatrix.sync.aligned.m8n8.x4.trans.shared.b16 {%0,%1,%2,%3}, [%4];" \
                 : "=r"(R0), "=r"(R1), "=r"(R2), "=r"(R3) : "r"(A))

__device__ __forceinline__ void mma_f16(float* d, const unsigned* a, const unsigned* b) {
    asm volatile(
        "mma.sync.aligned.m16n8k16.row.col.f32.f16.f16.f32 "
        "{%0,%1,%2,%3}, {%4,%5,%6,%7}, {%8,%9}, {%0,%1,%2,%3};"
        : "+f"(d[0]), "+f"(d[1]), "+f"(d[2]), "+f"(d[3])
        : "r"(a[0]), "r"(a[1]), "r"(a[2]), "r"(a[3]), "r"(b[0]), "r"(b[1]));
}

__device__ __forceinline__ unsigned exp2_f16x2(float a, float b) {
    unsigned r;
    asm volatile("{\n\t.reg .b32 t;\n\t"
                 "cvt.rn.f16x2.f32 t, %2, %1;\n\t"
                 "ex2.approx.f16x2 %0, t;\n\t}"
                 : "=r"(r) : "f"(a), "f"(b));
    return r;
}
__device__ __forceinline__ unsigned hadd2u(unsigned a, unsigned b) {
    unsigned r;
    asm volatile("add.f16x2 %0, %1, %2;" : "=r"(r) : "r"(a), "r"(b));
    return r;
}

// ---------------- weight prep: all fp16 hi only -------------------------------
struct SplitArgs {
    const float* w[5];
    __half* h[5];
};

__global__ __launch_bounds__(256)
void split5(SplitArgs a)
{
    const int i = blockIdx.x * 256 + threadIdx.x;
    if (i >= D * D) return;
    const int m = blockIdx.y;
    a.h[m][i] = __float2half_rn(a.w[m][i]);
}

// ---------------- LayerNorm: coalesced transpose-tile ------------------------
#define LN_SMEMB (768 * 33 * 4 + 256)

__global__ __launch_bounds__(256)
void ln_kernel(const float* __restrict__ x,
               const float* __restrict__ gamma,
               const float* __restrict__ beta)
{
    extern __shared__ float lsm[];
    float* st = lsm;
    float* mu = lsm + 768 * 33;
    float* rs = mu + 32;

    const int tid = threadIdx.x;
    const int b   = blockIdx.x >> 5;
    const int t0  = (blockIdx.x & 31) * 32;
    const float* xp = x + (size_t)b * D * T + t0;

    float gm[3], bt[3];
    #pragma unroll
    for (int j = 0; j < 3; ++j) {
        gm[j] = gamma[j * 256 + tid];
        bt[j] = beta [j * 256 + tid];
    }

    #pragma unroll 4
    for (int i = 0; i < 96; ++i) {
        const int idx = i * 256 + tid;
        const int c   = idx >> 5;
        const int tt  = idx & 31;
        st[c * 33 + tt] = xp[(size_t)c * T + tt];
    }
    __syncthreads();

    const int wid = tid >> 5, lane = tid & 31;
    #pragma unroll
    for (int rep = 0; rep < 4; ++rep) {
        const int tt = wid + rep * 8;
        float s = 0.f, ss = 0.f;
        #pragma unroll
        for (int j = 0; j < 24; ++j) {
            const float v = st[(lane + 32 * j) * 33 + tt];
            s += v; ss += v * v;
        }
        #pragma unroll
        for (int o = 16; o > 0; o >>= 1) {
            s  += __shfl_xor_sync(0xffffffffu, s,  o);
            ss += __shfl_xor_sync(0xffffffffu, ss, o);
        }
        if (lane == 0) {
            const float m = s * (1.0f / (float)D);
            const float var = ss * (1.0f / (float)D) - m * m;
            mu[tt] = m;
            rs[tt] = rsqrtf(var + 1e-5f);
        }
    }
    __syncthreads();

    for (int tt = 0; tt < 32; ++tt) {
        const float m = mu[tt], r = rs[tt];
        __half* o = g_xn + (size_t)(b * T + t0 + tt) * D;
        #pragma unroll
        for (int j = 0; j < 3; ++j) {
            const int c = j * 256 + tid;
            o[c] = __float2half_rn((st[c * 33 + tt] - m) * r * gm[j] + bt[j]);
        }
    }
}

// ---------------- fp16 tensor-core GEMM (1-pass, BK=32, 5-stage) --------------
// MODE 0: qkvg (fused 4-region). MODE 1: Wo, transposed output.
struct GemmArgs {
    const __half* B[4];
    const float* bias[4];
    float*       C[4];
};

#define URO    20
#define CROWB  80
#define CSTGB  10240
#define STGB_Q 20480            // stage bytes (A + B)
#define GEMM_SMEM (5 * STGB_Q)  // 102400

template<int MODE>
__global__ __launch_bounds__(256, 2)
void gemm_mma(const __half* __restrict__ Ag, GemmArgs args)
{
    extern __shared__ unsigned smu[];
    const int tid = threadIdx.x;
    const int m0  = blockIdx.y * 128;

    int region, nloc0;
    if (MODE == 0) { region = blockIdx.x / 6; nloc0 = (blockIdx.x % 6) * 128; }
    else           { region = 0;              nloc0 = blockIdx.x * 128; }
    const __half* B   = args.B[region];
    const float* bias = args.bias[region];
    float*       C    = args.C[region];

    const int rw  = tid >> 1;
    const int ch0 = (tid & 1) * 16;
    const __half* pA = Ag + (size_t)(m0 + rw) * D + ch0;
    const __half* pB = B  + (size_t)(nloc0 + rw) * D + ch0;
    const unsigned sbase = (unsigned)__cvta_generic_to_shared(smu);
    const unsigned soff  = (unsigned)(rw * CROWB + ch0 * 2);

    auto load_stage = [&](int kt, int buf) {
        const unsigned b0 = sbase + (unsigned)buf * STGB_Q + soff;
        CPASYNC(b0,              pA + kt);
        CPASYNC(b0 + 16u,        pA + kt + 8);
        CPASYNC(b0 + CSTGB,      pB + kt);
        CPASYNC(b0 + CSTGB + 16u,pB + kt + 8);
        CP_COMMIT();
    };

    const int w    = tid >> 5;
    const int lane = tid & 31;
    const int wm   = w >> 2;
    const int wn   = w & 3;
    const int lr   = lane >> 2;
    const int lc   = lane & 3;

    const int aRow  = (lane & 7) + ((lane & 8) ? 8 : 0);
    const int aColU = (lane & 16) ? 4 : 0;
    const int bRow  = (lane & 7) + ((lane & 16) ? 8 : 0);
    const int bColU = (lane & 8) ? 4 : 0;
    const unsigned aOff = (unsigned)(((wm * 64 + aRow) * URO + aColU) * 4);
    const unsigned bOff = (unsigned)(((wn * 32 + bRow) * URO + bColU) * 4);

    float acc[4][4][4];
    #pragma unroll
    for (int i = 0; i < 4; i++)
        #pragma unroll
        for (int j = 0; j < 4; j++)
            #pragma unroll
            for (int q = 0; q < 4; q++) acc[i][j][q] = 0.f;

    const int NIT = D / 32;   // 24
    #pragma unroll
    for (int s = 0; s < 4; ++s)
        load_stage(s * 32, s);

    for (int it = 0; it < NIT; ++it) {
        const int rem = NIT - 1 - it;
        if      (rem >= 3) { CP_WAIT(3); }
        else if (rem == 2) { CP_WAIT(2); }
        else if (rem == 1) { CP_WAIT(1); }
        else               { CP_WAIT(0); }
        __syncthreads();
        if (it + 4 < NIT)
            load_stage((it + 4) * 32, (it + 4) % 5);

        const unsigned stgb = sbase + (unsigned)((it % 5) * STGB_Q);

        #pragma unroll
        for (int ks = 0; ks < 2; ++ks) {
            const unsigned ko = (unsigned)(ks * 32);
            const unsigned aA = stgb + aOff + ko;
            const unsigned bB = stgb + CSTGB + bOff + ko;

            unsigned ah[4][4];
            #pragma unroll
            for (int mt = 0; mt < 4; ++mt)
                LDSM4(ah[mt][0], ah[mt][1], ah[mt][2], ah[mt][3],
                      aA + (unsigned)(mt * 16 * URO * 4));

            unsigned bh[4][2];
            {
                unsigned r0, r1, r2, r3;
                LDSM4(r0, r1, r2, r3, bB);
                bh[0][0] = r0; bh[0][1] = r1; bh[1][0] = r2; bh[1][1] = r3;
                LDSM4(r0, r1, r2, r3, bB + (unsigned)(16 * URO * 4));
                bh[2][0] = r0; bh[2][1] = r1; bh[3][0] = r2; bh[3][1] = r3;
            }
            #pragma unroll
            for (int mt = 0; mt < 4; ++mt)
                #pragma unroll
                for (int nt = 0; nt < 4; ++nt)
                    mma_f16(acc[mt][nt], ah[mt], bh[nt]);
        }
    }

    if (MODE == 0) {
        #pragma unroll
        for (int mt = 0; mt < 4; ++mt) {
            const int r = m0 + wm * 64 + mt * 16 + lr;
            #pragma unroll
            for (int nt = 0; nt < 4; ++nt) {
                const int n = nloc0 + wn * 32 + nt * 8 + lc * 2;
                float v00 = acc[mt][nt][0] + bias[n];
                float v01 = acc[mt][nt][1] + bias[n + 1];
                float v10 = acc[mt][nt][2] + bias[n];
                float v11 = acc[mt][nt][3] + bias[n + 1];
                const int head = n >> 6, wi = n & 63;
                if (region < 3) {
                    __half* dst = (region == 0) ? g_q16 : (region == 1) ? g_k16 : g_v16;
                    const float sc = (region == 0) ? QSCALE : 1.0f;
                    const size_t b0 = ((size_t)r * NH + head) * 64 + wi;
                    const size_t b1 = ((size_t)(r + 8) * NH + head) * 64 + wi;
                    *(__half2*)(dst + b0) = __floats2half2_rn(v00 * sc, v01 * sc);
                    *(__half2*)(dst + b1) = __floats2half2_rn(v10 * sc, v11 * sc);
                } else {
                    v00 = 1.0f / (1.0f + __expf(-v00));
                    v01 = 1.0f / (1.0f + __expf(-v01));
                    v10 = 1.0f / (1.0f + __expf(-v10));
                    v11 = 1.0f / (1.0f + __expf(-v11));
                    *(float2*)(C + (size_t)r * D + n)       = make_float2(v00, v01);
                    *(float2*)(C + (size_t)(r + 8) * D + n) = make_float2(v10, v11);
                }
            }
        }
    } else {
        // coalesced output transpose via smem (stride 132, conflict-free)
        __syncthreads();
        float* sC = (float*)smu;
        #pragma unroll
        for (int mt = 0; mt < 4; ++mt) {
            const int tloc = wm * 64 + mt * 16 + lr;
            #pragma unroll
            for (int nt = 0; nt < 4; ++nt) {
                const int nl = wn * 32 + nt * 8 + lc * 2;
                sC[(size_t)nl * 132 + tloc]           = acc[mt][nt][0] + bias[nloc0 + nl];
                sC[(size_t)(nl + 1) * 132 + tloc]     = acc[mt][nt][1] + bias[nloc0 + nl + 1];
                sC[(size_t)nl * 132 + tloc + 8]       = acc[mt][nt][2] + bias[nloc0 + nl];
                sC[(size_t)(nl + 1) * 132 + tloc + 8] = acc[mt][nt][3] + bias[nloc0 + nl + 1];
            }
        }
        __syncthreads();
        const int b = m0 >> 10, t0 = m0 & 1023;
        #pragma unroll
        for (int i = 0; i < 16; ++i) {
            const int idx = tid + i * 256;
            const int nl  = idx >> 5;
            const int tc  = (idx & 31) * 4;
            const float4 v = *(const float4*)&sC[(size_t)nl * 132 + tc];
            *(float4*)(C + ((size_t)b * D + nloc0 + nl) * T + t0 + tc) = v;
        }
    }
}

// ---------------- fp16 flash attention: 4 warps x 32 q-rows (R14 form) --------
#define KT      32
#define NITER   (T/KT)     // 32
#define KVROWH  72
#define STG_B   9216
#define ASTAGES 4
#define ATTN_SMEMB (ASTAGES * STG_B)   // 36864

__global__ __launch_bounds__(128, 3)
void attn_mma()
{
    extern __shared__ __half smh[];
    const int tid  = threadIdx.x;
    const int w    = tid >> 5;
    const int lane = tid & 31;
    const int lr   = lane >> 2;
    const int lc   = lane & 3;

    const int qt = blockIdx.x;
    const int h  = blockIdx.y;
    const int b  = blockIdx.z;
    const int row0 = b * T + qt * 128;
    const unsigned sb = (unsigned)__cvta_generic_to_shared(smh);

    auto load_kv = [&](int kt, int stg) {
        #pragma unroll
        for (int i = 0; i < 2; ++i) {
            const int id = tid + i * 128;
            const int tk = id >> 3;
            const int c  = (id & 7) * 8;
            const size_t g = ((size_t)(b * T + kt * KT + tk) * NH + h) * 64 + c;
            const unsigned d = sb + (unsigned)(stg * STG_B) +
                               (unsigned)((tk * KVROWH + c) * 2);
            CPASYNC(d,        g_k16 + g);
            CPASYNC(d + 4608, g_v16 + g);
        }
        CP_COMMIT();
    };
    #pragma unroll
    for (int s = 0; s < ASTAGES - 1; ++s)
        load_kv(s, s);

    unsigned qh[2][4][4];
    #pragma unroll
    for (int grp = 0; grp < 2; ++grp) {
        const __half* r0p = g_q16 +
            ((size_t)(row0 + w * 32 + grp * 16 + lr) * NH + h) * 64;
        const __half* r1p = r0p + (size_t)8 * NH * 64;
        #pragma unroll
        for (int ks = 0; ks < 4; ++ks) {
            const int c = ks * 16 + 2 * lc;
            qh[grp][ks][0] = *(const unsigned*)(r0p + c);
            qh[grp][ks][1] = *(const unsigned*)(r1p + c);
            qh[grp][ks][2] = *(const unsigned*)(r0p + c + 8);
            qh[grp][ks][3] = *(const unsigned*)(r1p + c + 8);
        }
    }

    float Oa[2][8][4];
    #pragma unroll
    for (int grp = 0; grp < 2; ++grp)
        #pragma unroll
        for (int nt = 0; nt < 8; ++nt)
            #pragma unroll
            for (int q = 0; q < 4; q++) Oa[grp][nt][q] = 0.f;
    float lg[2][2] = {{0.f, 0.f}, {0.f, 0.f}};

    const int kRow  = (lane & 7) + ((lane & 16) ? 8 : 0);
    const int kColH = (lane & 8) ? 8 : 0;
    const int vRow  = (lane & 7) + ((lane & 8) ? 8 : 0);
    const int vColH = (lane & 16) ? 8 : 0;

    for (int kt = 0; kt < NITER; ++kt) {
        const int rem = NITER - 1 - kt;
        if      (rem >= 2) { CP_WAIT(2); }
        else if (rem == 1) { CP_WAIT(1); }
        else               { CP_WAIT(0); }
        __syncthreads();
        if (kt + ASTAGES - 1 < NITER)
            load_kv(kt + ASTAGES - 1, (kt + ASTAGES - 1) % ASTAGES);

        const unsigned sK = sb + (unsigned)((kt % ASTAGES) * STG_B);
        const unsigned sV = sK + 4608;

        float sacc[2][4][4];
        #pragma unroll
        for (int grp = 0; grp < 2; ++grp)
            #pragma unroll
            for (int nt = 0; nt < 4; ++nt)
                #pragma unroll
                for (int q = 0; q < 4; q++) sacc[grp][nt][q] = 0.f;

        #pragma unroll
        for (int ks = 0; ks < 4; ++ks) {
            unsigned kh[4][2];
            {
                const unsigned a0 = sK +
                    (unsigned)((kRow * KVROWH + ks * 16 + kColH) * 2);
                unsigned r0, r1, r2, r3;
                LDSM4(r0, r1, r2, r3, a0);
                kh[0][0] = r0; kh[0][1] = r1; kh[1][0] = r2; kh[1][1] = r3;
                LDSM4(r0, r1, r2, r3, a0 + (unsigned)(16 * KVROWH * 2));
                kh[2][0] = r0; kh[2][1] = r1; kh[3][0] = r2; kh[3][1] = r3;
            }
            #pragma unroll
            for (int nt = 0; nt < 4; ++nt) {
                mma_f16(sacc[0][nt], qh[0][ks], kh[nt]);
                mma_f16(sacc[1][nt], qh[1][ks], kh[nt]);
            }
        }

        unsigned p16[2][2][4];
        #pragma unroll
        for (int grp = 0; grp < 2; ++grp) {
            #pragma unroll
            for (int nt = 0; nt < 4; ++nt) {
                p16[grp][nt >> 1][(nt & 1) * 2] =
                    exp2_f16x2(sacc[grp][nt][0], sacc[grp][nt][1]);
                p16[grp][nt >> 1][(nt & 1) * 2 + 1] =
                    exp2_f16x2(sacc[grp][nt][2], sacc[grp][nt][3]);
            }
            const unsigned s0a = hadd2u(p16[grp][0][0], p16[grp][0][2]);
            const unsigned s0b = hadd2u(p16[grp][1][0], p16[grp][1][2]);
            const unsigned s1a = hadd2u(p16[grp][0][1], p16[grp][0][3]);
            const unsigned s1b = hadd2u(p16[grp][1][1], p16[grp][1][3]);
            const float2 f0a = __half22float2(*(const __half2*)&s0a);
            const float2 f0b = __half22float2(*(const __half2*)&s0b);
            const float2 f1a = __half22float2(*(const __half2*)&s1a);
            const float2 f1b = __half22float2(*(const __half2*)&s1b);
            lg[grp][0] += (f0a.x + f0a.y) + (f0b.x + f0b.y);
            lg[grp][1] += (f1a.x + f1a.y) + (f1b.x + f1b.y);
        }

        #pragma unroll
        for (int g = 0; g < 2; ++g) {
            #pragma unroll
            for (int p = 0; p < 4; ++p) {
                const unsigned a0 = sV +
                    (unsigned)(((g * 16 + vRow) * KVROWH + p * 16 + vColH) * 2);
                unsigned vh[2][2];
                unsigned r0, r1, r2, r3;
                LDSM4T(r0, r1, r2, r3, a0);
                vh[0][0] = r0; vh[0][1] = r1; vh[1][0] = r2; vh[1][1] = r3;
                mma_f16(Oa[0][2*p],     p16[0][g], vh[0]);
                mma_f16(Oa[0][2*p + 1], p16[0][g], vh[1]);
                mma_f16(Oa[1][2*p],     p16[1][g], vh[0]);
                mma_f16(Oa[1][2*p + 1], p16[1][g], vh[1]);
            }
        }
    }

    #pragma unroll
    for (int grp = 0; grp < 2; ++grp) {
        float l0 = lg[grp][0], l1 = lg[grp][1];
        l0 += __shfl_xor_sync(0xffffffffu, l0, 1);
        l0 += __shfl_xor_sync(0xffffffffu, l0, 2);
        l1 += __shfl_xor_sync(0xffffffffu, l1, 1);
        l1 += __shfl_xor_sync(0xffffffffu, l1, 2);
        const float inv0 = 1.0f / l0;
        const float inv1 = 1.0f / l1;
        const int gr0 = row0 + w * 32 + grp * 16 + lr;
        const int gr1 = gr0 + 8;
        const int col0 = h * DH;
        #pragma unroll
        for (int nt = 0; nt < 8; ++nt) {
            const int c = col0 + nt * 8 + 2 * lc;
            const float2 ga = *(const float2*)(g_g + (size_t)gr0 * D + c);
            const float2 gb = *(const float2*)(g_g + (size_t)gr1 * D + c);
            *(__half2*)(g_y16 + (size_t)gr0 * D + c) =
                __floats2half2_rn(Oa[grp][nt][0] * inv0 * ga.x,
                                  Oa[grp][nt][1] * inv0 * ga.y);
            *(__half2*)(g_y16 + (size_t)gr1 * D + c) =
                __floats2half2_rn(Oa[grp][nt][2] * inv1 * gb.x,
                                  Oa[grp][nt][3] * inv1 * gb.y);
        }
    }
}

// ---------------- launch --------------------------------------------------------
extern "C" void kernel_launch(void* const* d_in, const int* in_sizes, int n_in,
                              void* d_out, int out_size)
{
    const float* x     = (const float*)d_in[0];
    const float* Wq    = (const float*)d_in[1];
    const float* bq    = (const float*)d_in[2];
    const float* Wk    = (const float*)d_in[3];
    const float* bk    = (const float*)d_in[4];
    const float* Wv    = (const float*)d_in[5];
    const float* bv    = (const float*)d_in[6];
    const float* Wo    = (const float*)d_in[7];
    const float* bo    = (const float*)d_in[8];
    const float* Wg    = (const float*)d_in[9];
    const float* bg    = (const float*)d_in[10];
    const float* gamma = (const float*)d_in[11];
    const float* beta  = (const float*)d_in[12];
    float* out = (float*)d_out;

    void *p;
    __half *xn, *y16;
    __half *wq,*wk,*wv,*wg,*wo;
    float *gb_;
    cudaGetSymbolAddress(&p, g_xn);   xn = (__half*)p;
    cudaGetSymbolAddress(&p, g_y16); y16 = (__half*)p;
    cudaGetSymbolAddress(&p, g_g);   gb_ = (float*)p;
    cudaGetSymbolAddress(&p, g_wq);   wq = (__half*)p;
    cudaGetSymbolAddress(&p, g_wk);   wk = (__half*)p;
    cudaGetSymbolAddress(&p, g_wv);   wv = (__half*)p;
    cudaGetSymbolAddress(&p, g_wg);   wg = (__half*)p;
    cudaGetSymbolAddress(&p, g_wo);   wo = (__half*)p;

    cudaFuncSetAttribute(gemm_mma<0>, cudaFuncAttributeMaxDynamicSharedMemorySize, GEMM_SMEM);
    cudaFuncSetAttribute(gemm_mma<1>, cudaFuncAttributeMaxDynamicSharedMemorySize, GEMM_SMEM);
    cudaFuncSetAttribute(attn_mma, cudaFuncAttributeMaxDynamicSharedMemorySize, ATTN_SMEMB);
    cudaFuncSetAttribute(ln_kernel, cudaFuncAttributeMaxDynamicSharedMemorySize, LN_SMEMB);

    const int wblocks = (D * D + 255) / 256;
    {
        SplitArgs sa;
        sa.w[0] = Wq; sa.h[0] = wq;
        sa.w[1] = Wk; sa.h[1] = wk;
        sa.w[2] = Wv; sa.h[2] = wv;
        sa.w[3] = Wg; sa.h[3] = wg;
        sa.w[4] = Wo; sa.h[4] = wo;
        split5<<<dim3(wblocks, 5), 256>>>(sa);
    }

    ln_kernel<<<256, 256, LN_SMEMB>>>(x, gamma, beta);

    {
        GemmArgs a;
        a.B[0] = wq; a.bias[0] = bq; a.C[0] = nullptr;
        a.B[1] = wk; a.bias[1] = bk; a.C[1] = nullptr;
        a.B[2] = wv; a.bias[2] = bv; a.C[2] = nullptr;
        a.B[3] = wg; a.bias[3] = bg; a.C[3] = gb_;
        gemm_mma<0><<<dim3(24, 64), 256, GEMM_SMEM>>>(xn, a);
    }

    attn_mma<<<dim3(8, NH, BATCH), 128, ATTN_SMEMB>>>();

    {
        GemmArgs a;
        a.B[0] = wo; a.bias[0] = bo; a.C[0] = out;
        a.B[1] = a.B[2] = a.B[3] = wo;
        a.bias[1] = a.bias[2] = a.bias[3] = bo;
        a.C[1] = a.C[2] = a.C[3] = out;
        gemm_mma<1><<<dim3(6, 64), 256, GEMM_SMEM>>>(y16, a);
    }
}

// round 17
// speedup vs baseline: 1.2903x; 1.0142x over previous
#include <cuda_runtime.h>
#include <cuda_fp16.h>
#include <math.h>

#define D      768
#define T      1024
#define BATCH  8
#define M_TOT  (BATCH*T)   // 8192
#define NH     12
#define DH     64

// ---------------- scratch (device globals: alloc-free rule) ----------------
__device__ __half g_xn [(size_t)M_TOT * D];            // fp16 single
__device__ __half g_q16[(size_t)M_TOT * NH * 64];      // [tok][head][64], QSCALE folded
__device__ __half g_k16[(size_t)M_TOT * NH * 64];
__device__ __half g_v16[(size_t)M_TOT * NH * 64];
__device__ float  g_g  [(size_t)M_TOT * D];
__device__ __half g_y16[(size_t)M_TOT * D];
__device__ __half g_wq[D*D];
__device__ __half g_wk[D*D];
__device__ __half g_wv[D*D];
__device__ __half g_wg[D*D];
__device__ __half g_wo[D*D];

#define QSCALE 0.18033688011112042f

// ---------------- PTX helpers -----------------------------------------------
#define CPASYNC(dst, src) \
    asm volatile("cp.async.cg.shared.global [%0], [%1], 16;" :: "r"(dst), "l"(src) : "memory")
#define CP_COMMIT() asm volatile("cp.async.commit_group;" ::: "memory")
#define CP_WAIT(n)  asm volatile("cp.async.wait_group %0;" :: "n"(n) : "memory")
#define LDSM4(R0,R1,R2,R3,A) \
    asm volatile("ldmatrix.sync.aligned.m8n8.x4.shared.b16 {%0,%1,%2,%3}, [%4];" \
                 : "=r"(R0), "=r"(R1), "=r"(R2), "=r"(R3) : "r"(A))
#define LDSM4T(R0,R1,R2,R3,A) \
    asm volatile("ldmatrix.sync.aligned.m8n8.x4.trans.shared.b16 {%0,%1,%2,%3}, [%4];" \
                 : "=r"(R0), "=r"(R1), "=r"(R2), "=r"(R3) : "r"(A))

__device__ __forceinline__ void mma_f16(float* d, const unsigned* a, const unsigned* b) {
    asm volatile(
        "mma.sync.aligned.m16n8k16.row.col.f32.f16.f16.f32 "
        "{%0,%1,%2,%3}, {%4,%5,%6,%7}, {%8,%9}, {%0,%1,%2,%3};"
        : "+f"(d[0]), "+f"(d[1]), "+f"(d[2]), "+f"(d[3])
        : "r"(a[0]), "r"(a[1]), "r"(a[2]), "r"(a[3]), "r"(b[0]), "r"(b[1]));
}

// fp16-accumulate variant (2x HMMA rate); D/C are 2 packed f16x2 regs
__device__ __forceinline__ void mma_f16acc(unsigned* d, const unsigned* a, const unsigned* b) {
    asm volatile(
        "mma.sync.aligned.m16n8k16.row.col.f16.f16.f16.f16 "
        "{%0,%1}, {%2,%3,%4,%5}, {%6,%7}, {%0,%1};"
        : "+r"(d[0]), "+r"(d[1])
        : "r"(a[0]), "r"(a[1]), "r"(a[2]), "r"(a[3]), "r"(b[0]), "r"(b[1]));
}

__device__ __forceinline__ unsigned exp2_f16x2u(unsigned s) {
    unsigned r;
    asm volatile("ex2.approx.f16x2 %0, %1;" : "=r"(r) : "r"(s));
    return r;
}
__device__ __forceinline__ unsigned hadd2u(unsigned a, unsigned b) {
    unsigned r;
    asm volatile("add.f16x2 %0, %1, %2;" : "=r"(r) : "r"(a), "r"(b));
    return r;
}

// ---------------- weight prep: all fp16 -------------------------------------
struct SplitArgs {
    const float* w[5];
    __half* h[5];
};

__global__ __launch_bounds__(256)
void split5(SplitArgs a)
{
    const int i = blockIdx.x * 256 + threadIdx.x;
    if (i >= D * D) return;
    const int m = blockIdx.y;
    a.h[m][i] = __float2half_rn(a.w[m][i]);
}

// ---------------- LayerNorm: coalesced transpose-tile ------------------------
#define LN_SMEMB (768 * 33 * 4 + 256)

__global__ __launch_bounds__(256)
void ln_kernel(const float* __restrict__ x,
               const float* __restrict__ gamma,
               const float* __restrict__ beta)
{
    extern __shared__ float lsm[];
    float* st = lsm;
    float* mu = lsm + 768 * 33;
    float* rs = mu + 32;

    const int tid = threadIdx.x;
    const int b   = blockIdx.x >> 5;
    const int t0  = (blockIdx.x & 31) * 32;
    const float* xp = x + (size_t)b * D * T + t0;

    float gm[3], bt[3];
    #pragma unroll
    for (int j = 0; j < 3; ++j) {
        gm[j] = gamma[j * 256 + tid];
        bt[j] = beta [j * 256 + tid];
    }

    #pragma unroll 4
    for (int i = 0; i < 96; ++i) {
        const int idx = i * 256 + tid;
        const int c   = idx >> 5;
        const int tt  = idx & 31;
        st[c * 33 + tt] = xp[(size_t)c * T + tt];
    }
    __syncthreads();

    const int wid = tid >> 5, lane = tid & 31;
    #pragma unroll
    for (int rep = 0; rep < 4; ++rep) {
        const int tt = wid + rep * 8;
        float s = 0.f, ss = 0.f;
        #pragma unroll
        for (int j = 0; j < 24; ++j) {
            const float v = st[(lane + 32 * j) * 33 + tt];
            s += v; ss += v * v;
        }
        #pragma unroll
        for (int o = 16; o > 0; o >>= 1) {
            s  += __shfl_xor_sync(0xffffffffu, s,  o);
            ss += __shfl_xor_sync(0xffffffffu, ss, o);
        }
        if (lane == 0) {
            const float m = s * (1.0f / (float)D);
            const float var = ss * (1.0f / (float)D) - m * m;
            mu[tt] = m;
            rs[tt] = rsqrtf(var + 1e-5f);
        }
    }
    __syncthreads();

    for (int tt = 0; tt < 32; ++tt) {
        const float m = mu[tt], r = rs[tt];
        __half* o = g_xn + (size_t)(b * T + t0 + tt) * D;
        #pragma unroll
        for (int j = 0; j < 3; ++j) {
            const int c = j * 256 + tid;
            o[c] = __float2half_rn((st[c * 33 + tt] - m) * r * gm[j] + bt[j]);
        }
    }
}

// ---------------- fp16 tensor-core GEMM (1-pass, BK=32, 5-stage) --------------
struct GemmArgs {
    const __half* B[4];
    const float* bias[4];
    float*       C[4];
};

#define URO    20
#define CROWB  80
#define CSTGB  10240
#define STGB_Q 20480
#define GEMM_SMEM (5 * STGB_Q)  // 102400

template<int MODE>
__global__ __launch_bounds__(256, 2)
void gemm_mma(const __half* __restrict__ Ag, GemmArgs args)
{
    extern __shared__ unsigned smu[];
    const int tid = threadIdx.x;
    const int m0  = blockIdx.y * 128;

    int region, nloc0;
    if (MODE == 0) { region = blockIdx.x / 6; nloc0 = (blockIdx.x % 6) * 128; }
    else           { region = 0;              nloc0 = blockIdx.x * 128; }
    const __half* B   = args.B[region];
    const float* bias = args.bias[region];
    float*       C    = args.C[region];

    const int rw  = tid >> 1;
    const int ch0 = (tid & 1) * 16;
    const __half* pA = Ag + (size_t)(m0 + rw) * D + ch0;
    const __half* pB = B  + (size_t)(nloc0 + rw) * D + ch0;
    const unsigned sbase = (unsigned)__cvta_generic_to_shared(smu);
    const unsigned soff  = (unsigned)(rw * CROWB + ch0 * 2);

    auto load_stage = [&](int kt, int buf) {
        const unsigned b0 = sbase + (unsigned)buf * STGB_Q + soff;
        CPASYNC(b0,              pA + kt);
        CPASYNC(b0 + 16u,        pA + kt + 8);
        CPASYNC(b0 + CSTGB,      pB + kt);
        CPASYNC(b0 + CSTGB + 16u,pB + kt + 8);
        CP_COMMIT();
    };

    const int w    = tid >> 5;
    const int lane = tid & 31;
    const int wm   = w >> 2;
    const int wn   = w & 3;
    const int lr   = lane >> 2;
    const int lc   = lane & 3;

    const int aRow  = (lane & 7) + ((lane & 8) ? 8 : 0);
    const int aColU = (lane & 16) ? 4 : 0;
    const int bRow  = (lane & 7) + ((lane & 16) ? 8 : 0);
    const int bColU = (lane & 8) ? 4 : 0;
    const unsigned aOff = (unsigned)(((wm * 64 + aRow) * URO + aColU) * 4);
    const unsigned bOff = (unsigned)(((wn * 32 + bRow) * URO + bColU) * 4);

    float acc[4][4][4];
    #pragma unroll
    for (int i = 0; i < 4; i++)
        #pragma unroll
        for (int j = 0; j < 4; j++)
            #pragma unroll
            for (int q = 0; q < 4; q++) acc[i][j][q] = 0.f;

    const int NIT = D / 32;   // 24
    #pragma unroll
    for (int s = 0; s < 4; ++s)
        load_stage(s * 32, s);

    for (int it = 0; it < NIT; ++it) {
        const int rem = NIT - 1 - it;
        if      (rem >= 3) { CP_WAIT(3); }
        else if (rem == 2) { CP_WAIT(2); }
        else if (rem == 1) { CP_WAIT(1); }
        else               { CP_WAIT(0); }
        __syncthreads();
        if (it + 4 < NIT)
            load_stage((it + 4) * 32, (it + 4) % 5);

        const unsigned stgb = sbase + (unsigned)((it % 5) * STGB_Q);

        #pragma unroll
        for (int ks = 0; ks < 2; ++ks) {
            const unsigned ko = (unsigned)(ks * 32);
            const unsigned aA = stgb + aOff + ko;
            const unsigned bB = stgb + CSTGB + bOff + ko;

            unsigned ah[4][4];
            #pragma unroll
            for (int mt = 0; mt < 4; ++mt)
                LDSM4(ah[mt][0], ah[mt][1], ah[mt][2], ah[mt][3],
                      aA + (unsigned)(mt * 16 * URO * 4));

            unsigned bh[4][2];
            {
                unsigned r0, r1, r2, r3;
                LDSM4(r0, r1, r2, r3, bB);
                bh[0][0] = r0; bh[0][1] = r1; bh[1][0] = r2; bh[1][1] = r3;
                LDSM4(r0, r1, r2, r3, bB + (unsigned)(16 * URO * 4));
                bh[2][0] = r0; bh[2][1] = r1; bh[3][0] = r2; bh[3][1] = r3;
            }
            #pragma unroll
            for (int mt = 0; mt < 4; ++mt)
                #pragma unroll
                for (int nt = 0; nt < 4; ++nt)
                    mma_f16(acc[mt][nt], ah[mt], bh[nt]);
        }
    }

    if (MODE == 0) {
        #pragma unroll
        for (int mt = 0; mt < 4; ++mt) {
            const int r = m0 + wm * 64 + mt * 16 + lr;
            #pragma unroll
            for (int nt = 0; nt < 4; ++nt) {
                const int n = nloc0 + wn * 32 + nt * 8 + lc * 2;
                float v00 = acc[mt][nt][0] + bias[n];
                float v01 = acc[mt][nt][1] + bias[n + 1];
                float v10 = acc[mt][nt][2] + bias[n];
                float v11 = acc[mt][nt][3] + bias[n + 1];
                const int head = n >> 6, wi = n & 63;
                if (region < 3) {
                    __half* dst = (region == 0) ? g_q16 : (region == 1) ? g_k16 : g_v16;
                    const float sc = (region == 0) ? QSCALE : 1.0f;
                    const size_t b0 = ((size_t)r * NH + head) * 64 + wi;
                    const size_t b1 = ((size_t)(r + 8) * NH + head) * 64 + wi;
                    *(__half2*)(dst + b0) = __floats2half2_rn(v00 * sc, v01 * sc);
                    *(__half2*)(dst + b1) = __floats2half2_rn(v10 * sc, v11 * sc);
                } else {
                    v00 = 1.0f / (1.0f + __expf(-v00));
                    v01 = 1.0f / (1.0f + __expf(-v01));
                    v10 = 1.0f / (1.0f + __expf(-v10));
                    v11 = 1.0f / (1.0f + __expf(-v11));
                    *(float2*)(C + (size_t)r * D + n)       = make_float2(v00, v01);
                    *(float2*)(C + (size_t)(r + 8) * D + n) = make_float2(v10, v11);
                }
            }
        }
    } else {
        __syncthreads();
        float* sC = (float*)smu;
        #pragma unroll
        for (int mt = 0; mt < 4; ++mt) {
            const int tloc = wm * 64 + mt * 16 + lr;
            #pragma unroll
            for (int nt = 0; nt < 4; ++nt) {
                const int nl = wn * 32 + nt * 8 + lc * 2;
                sC[(size_t)nl * 132 + tloc]           = acc[mt][nt][0] + bias[nloc0 + nl];
                sC[(size_t)(nl + 1) * 132 + tloc]     = acc[mt][nt][1] + bias[nloc0 + nl + 1];
                sC[(size_t)nl * 132 + tloc + 8]       = acc[mt][nt][2] + bias[nloc0 + nl];
                sC[(size_t)(nl + 1) * 132 + tloc + 8] = acc[mt][nt][3] + bias[nloc0 + nl + 1];
            }
        }
        __syncthreads();
        const int b = m0 >> 10, t0 = m0 & 1023;
        #pragma unroll
        for (int i = 0; i < 16; ++i) {
            const int idx = tid + i * 256;
            const int nl  = idx >> 5;
            const int tc  = (idx & 31) * 4;
            const float4 v = *(const float4*)&sC[(size_t)nl * 132 + tc];
            *(float4*)(C + ((size_t)b * D + nloc0 + nl) * T + t0 + tc) = v;
        }
    }
}

// ---------------- fp16 flash attention: QK fp16-accum, PV fp32-accum ----------
#define KT      32
#define NITER   (T/KT)     // 32
#define KVROWH  72
#define STG_B   9216
#define ASTAGES 4
#define ATTN_SMEMB (ASTAGES * STG_B)   // 36864

__global__ __launch_bounds__(128, 3)
void attn_mma()
{
    extern __shared__ __half smh[];
    const int tid  = threadIdx.x;
    const int w    = tid >> 5;
    const int lane = tid & 31;
    const int lr   = lane >> 2;
    const int lc   = lane & 3;

    const int qt = blockIdx.x;
    const int h  = blockIdx.y;
    const int b  = blockIdx.z;
    const int row0 = b * T + qt * 128;
    const unsigned sb = (unsigned)__cvta_generic_to_shared(smh);

    auto load_kv = [&](int kt, int stg) {
        #pragma unroll
        for (int i = 0; i < 2; ++i) {
            const int id = tid + i * 128;
            const int tk = id >> 3;
            const int c  = (id & 7) * 8;
            const size_t g = ((size_t)(b * T + kt * KT + tk) * NH + h) * 64 + c;
            const unsigned d = sb + (unsigned)(stg * STG_B) +
                               (unsigned)((tk * KVROWH + c) * 2);
            CPASYNC(d,        g_k16 + g);
            CPASYNC(d + 4608, g_v16 + g);
        }
        CP_COMMIT();
    };
    #pragma unroll
    for (int s = 0; s < ASTAGES - 1; ++s)
        load_kv(s, s);

    unsigned qh[2][4][4];
    #pragma unroll
    for (int grp = 0; grp < 2; ++grp) {
        const __half* r0p = g_q16 +
            ((size_t)(row0 + w * 32 + grp * 16 + lr) * NH + h) * 64;
        const __half* r1p = r0p + (size_t)8 * NH * 64;
        #pragma unroll
        for (int ks = 0; ks < 4; ++ks) {
            const int c = ks * 16 + 2 * lc;
            qh[grp][ks][0] = *(const unsigned*)(r0p + c);
            qh[grp][ks][1] = *(const unsigned*)(r1p + c);
            qh[grp][ks][2] = *(const unsigned*)(r0p + c + 8);
            qh[grp][ks][3] = *(const unsigned*)(r1p + c + 8);
        }
    }

    float Oa[2][8][4];
    #pragma unroll
    for (int grp = 0; grp < 2; ++grp)
        #pragma unroll
        for (int nt = 0; nt < 8; ++nt)
            #pragma unroll
            for (int q = 0; q < 4; q++) Oa[grp][nt][q] = 0.f;
    float lg[2][2] = {{0.f, 0.f}, {0.f, 0.f}};

    const int kRow  = (lane & 7) + ((lane & 16) ? 8 : 0);
    const int kColH = (lane & 8) ? 8 : 0;
    const int vRow  = (lane & 7) + ((lane & 8) ? 8 : 0);
    const int vColH = (lane & 16) ? 8 : 0;

    for (int kt = 0; kt < NITER; ++kt) {
        const int rem = NITER - 1 - kt;
        if      (rem >= 2) { CP_WAIT(2); }
        else if (rem == 1) { CP_WAIT(1); }
        else               { CP_WAIT(0); }
        __syncthreads();
        if (kt + ASTAGES - 1 < NITER)
            load_kv(kt + ASTAGES - 1, (kt + ASTAGES - 1) % ASTAGES);

        const unsigned sK = sb + (unsigned)((kt % ASTAGES) * STG_B);
        const unsigned sV = sK + 4608;

        // ---- S = Q K^T (fp16 accumulate, 2x rate) ----
        // sacc16[grp][nt] = {c0: (row lr, cols 2lc,2lc+1), c1: (row lr+8, ...)}
        unsigned sacc16[2][4][2];
        #pragma unroll
        for (int grp = 0; grp < 2; ++grp)
            #pragma unroll
            for (int nt = 0; nt < 4; ++nt) {
                sacc16[grp][nt][0] = 0u;
                sacc16[grp][nt][1] = 0u;
            }

        #pragma unroll
        for (int ks = 0; ks < 4; ++ks) {
            unsigned kh[4][2];
            {
                const unsigned a0 = sK +
                    (unsigned)((kRow * KVROWH + ks * 16 + kColH) * 2);
                unsigned r0, r1, r2, r3;
                LDSM4(r0, r1, r2, r3, a0);
                kh[0][0] = r0; kh[0][1] = r1; kh[1][0] = r2; kh[1][1] = r3;
                LDSM4(r0, r1, r2, r3, a0 + (unsigned)(16 * KVROWH * 2));
                kh[2][0] = r0; kh[2][1] = r1; kh[3][0] = r2; kh[3][1] = r3;
            }
            #pragma unroll
            for (int nt = 0; nt < 4; ++nt) {
                mma_f16acc(sacc16[0][nt], qh[0][ks], kh[nt]);
                mma_f16acc(sacc16[1][nt], qh[1][ks], kh[nt]);
            }
        }

        // ---- fixed-base softmax: p = 2^s directly on packed f16x2 ----
        unsigned p16[2][2][4];
        #pragma unroll
        for (int grp = 0; grp < 2; ++grp) {
            #pragma unroll
            for (int nt = 0; nt < 4; ++nt) {
                p16[grp][nt >> 1][(nt & 1) * 2]     = exp2_f16x2u(sacc16[grp][nt][0]);
                p16[grp][nt >> 1][(nt & 1) * 2 + 1] = exp2_f16x2u(sacc16[grp][nt][1]);
            }
            const unsigned s0a = hadd2u(p16[grp][0][0], p16[grp][0][2]);
            const unsigned s0b = hadd2u(p16[grp][1][0], p16[grp][1][2]);
            const unsigned s1a = hadd2u(p16[grp][0][1], p16[grp][0][3]);
            const unsigned s1b = hadd2u(p16[grp][1][1], p16[grp][1][3]);
            const float2 f0a = __half22float2(*(const __half2*)&s0a);
            const float2 f0b = __half22float2(*(const __half2*)&s0b);
            const float2 f1a = __half22float2(*(const __half2*)&s1a);
            const float2 f1b = __half22float2(*(const __half2*)&s1b);
            lg[grp][0] += (f0a.x + f0a.y) + (f0b.x + f0b.y);
            lg[grp][1] += (f1a.x + f1a.y) + (f1b.x + f1b.y);
        }

        // ---- O += P V (fp32 accumulate) ----
        #pragma unroll
        for (int g = 0; g < 2; ++g) {
            #pragma unroll
            for (int p = 0; p < 4; ++p) {
                const unsigned a0 = sV +
                    (unsigned)(((g * 16 + vRow) * KVROWH + p * 16 + vColH) * 2);
                unsigned vh[2][2];
                unsigned r0, r1, r2, r3;
                LDSM4T(r0, r1, r2, r3, a0);
                vh[0][0] = r0; vh[0][1] = r1; vh[1][0] = r2; vh[1][1] = r3;
                mma_f16(Oa[0][2*p],     p16[0][g], vh[0]);
                mma_f16(Oa[0][2*p + 1], p16[0][g], vh[1]);
                mma_f16(Oa[1][2*p],     p16[1][g], vh[0]);
                mma_f16(Oa[1][2*p + 1], p16[1][g], vh[1]);
            }
        }
    }

    #pragma unroll
    for (int grp = 0; grp < 2; ++grp) {
        float l0 = lg[grp][0], l1 = lg[grp][1];
        l0 += __shfl_xor_sync(0xffffffffu, l0, 1);
        l0 += __shfl_xor_sync(0xffffffffu, l0, 2);
        l1 += __shfl_xor_sync(0xffffffffu, l1, 1);
        l1 += __shfl_xor_sync(0xffffffffu, l1, 2);
        const float inv0 = 1.0f / l0;
        const float inv1 = 1.0f / l1;
        const int gr0 = row0 + w * 32 + grp * 16 + lr;
        const int gr1 = gr0 + 8;
        const int col0 = h * DH;
        #pragma unroll
        for (int nt = 0; nt < 8; ++nt) {
            const int c = col0 + nt * 8 + 2 * lc;
            const float2 ga = *(const float2*)(g_g + (size_t)gr0 * D + c);
            const float2 gb = *(const float2*)(g_g + (size_t)gr1 * D + c);
            *(__half2*)(g_y16 + (size_t)gr0 * D + c) =
                __floats2half2_rn(Oa[grp][nt][0] * inv0 * ga.x,
                                  Oa[grp][nt][1] * inv0 * ga.y);
            *(__half2*)(g_y16 + (size_t)gr1 * D + c) =
                __floats2half2_rn(Oa[grp][nt][2] * inv1 * gb.x,
                                  Oa[grp][nt][3] * inv1 * gb.y);
        }
    }
}

// ---------------- launch --------------------------------------------------------
extern "C" void kernel_launch(void* const* d_in, const int* in_sizes, int n_in,
                              void* d_out, int out_size)
{
    const float* x     = (const float*)d_in[0];
    const float* Wq    = (const float*)d_in[1];
    const float* bq    = (const float*)d_in[2];
    const float* Wk    = (const float*)d_in[3];
    const float* bk    = (const float*)d_in[4];
    const float* Wv    = (const float*)d_in[5];
    const float* bv    = (const float*)d_in[6];
    const float* Wo    = (const float*)d_in[7];
    const float* bo    = (const float*)d_in[8];
    const float* Wg    = (const float*)d_in[9];
    const float* bg    = (const float*)d_in[10];
    const float* gamma = (const float*)d_in[11];
    const float* beta  = (const float*)d_in[12];
    float* out = (float*)d_out;

    void *p;
    __half *xn, *y16;
    __half *wq,*wk,*wv,*wg,*wo;
    float *gb_;
    cudaGetSymbolAddress(&p, g_xn);   xn = (__half*)p;
    cudaGetSymbolAddress(&p, g_y16); y16 = (__half*)p;
    cudaGetSymbolAddress(&p, g_g);   gb_ = (float*)p;
    cudaGetSymbolAddress(&p, g_wq);   wq = (__half*)p;
    cudaGetSymbolAddress(&p, g_wk);   wk = (__half*)p;
    cudaGetSymbolAddress(&p, g_wv);   wv = (__half*)p;
    cudaGetSymbolAddress(&p, g_wg);   wg = (__half*)p;
    cudaGetSymbolAddress(&p, g_wo);   wo = (__half*)p;

    cudaFuncSetAttribute(gemm_mma<0>, cudaFuncAttributeMaxDynamicSharedMemorySize, GEMM_SMEM);
    cudaFuncSetAttribute(gemm_mma<1>, cudaFuncAttributeMaxDynamicSharedMemorySize, GEMM_SMEM);
    cudaFuncSetAttribute(attn_mma, cudaFuncAttributeMaxDynamicSharedMemorySize, ATTN_SMEMB);
    cudaFuncSetAttribute(ln_kernel, cudaFuncAttributeMaxDynamicSharedMemorySize, LN_SMEMB);

    const int wblocks = (D * D + 255) / 256;
    {
        SplitArgs sa;
        sa.w[0] = Wq; sa.h[0] = wq;
        sa.w[1] = Wk; sa.h[1] = wk;
        sa.w[2] = Wv; sa.h[2] = wv;
        sa.w[3] = Wg; sa.h[3] = wg;
        sa.w[4] = Wo; sa.h[4] = wo;
        split5<<<dim3(wblocks, 5), 256>>>(sa);
    }

    ln_kernel<<<256, 256, LN_SMEMB>>>(x, gamma, beta);

    {
        GemmArgs a;
        a.B[0] = wq; a.bias[0] = bq; a.C[0] = nullptr;
        a.B[1] = wk; a.bias[1] = bk; a.C[1] = nullptr;
        a.B[2] = wv; a.bias[2] = bv; a.C[2] = nullptr;
        a.B[3] = wg; a.bias[3] = bg; a.C[3] = gb_;
        gemm_mma<0><<<dim3(24, 64), 256, GEMM_SMEM>>>(xn, a);
    }

    attn_mma<<<dim3(8, NH, BATCH), 128, ATTN_SMEMB>>>();

    {
        GemmArgs a;
        a.B[0] = wo; a.bias[0] = bo; a.C[0] = out;
        a.B[1] = a.B[2] = a.B[3] = wo;
        a.bias[1] = a.bias[2] = a.bias[3] = bo;
        a.C[1] = a.C[2] = a.C[3] = out;
        gemm_mma<1><<<dim3(6, 64), 256, GEMM_SMEM>>>(y16, a);
    }
}